// round 4
// baseline (speedup 1.0000x reference)
#include <cuda_runtime.h>
#include <cstdint>

#define BATCH 8
#define NSEQ  4096
#define DIM   384
#define HEADS 6
#define DHEAD 64
#define INNER 384
#define ROWS  (BATCH*NSEQ)   // 32768

// ---- scratch (device globals: no allocation allowed) ----
__device__ float g_q   [ (size_t)ROWS*INNER ];
__device__ float g_k   [ (size_t)ROWS*INNER ];
__device__ float g_v   [ (size_t)ROWS*INNER ];
__device__ float g_attn[ (size_t)ROWS*INNER ];
__device__ float g_kv  [ BATCH*HEADS*DHEAD*DHEAD ];
__device__ float g_ksum[ BATCH*HEADS*DHEAD ];

__device__ __forceinline__ float elu1(float x) {
    return x > 0.f ? x + 1.f : __expf(x);
}

__device__ __forceinline__ uint32_t f2tf32(float x) {
    uint32_t u;
    asm("cvt.rna.tf32.f32 %0, %1;" : "=r"(u) : "f"(x));
    return u;
}

__device__ __forceinline__ uint32_t smem_u32(const void* p) {
    uint32_t a;
    asm("{ .reg .u64 t; cvta.to.shared.u64 t, %1; cvt.u32.u64 %0, t; }"
        : "=r"(a) : "l"(p));
    return a;
}

__device__ __forceinline__ void cp16(uint32_t dst, const void* src) {
    asm volatile("cp.async.cg.shared.global [%0], [%1], 16;"
                 :: "r"(dst), "l"(src));
}
#define CP_COMMIT() asm volatile("cp.async.commit_group;")
#define CP_WAIT0()  asm volatile("cp.async.wait_group 0;")

__device__ __forceinline__ void mma_tf32(float c[4], uint32_t a0, uint32_t a1,
                                         uint32_t a2, uint32_t a3,
                                         uint32_t b0, uint32_t b1) {
    asm volatile(
        "mma.sync.aligned.m16n8k8.row.col.f32.tf32.tf32.f32 "
        "{%0,%1,%2,%3}, {%4,%5,%6,%7}, {%8,%9}, {%0,%1,%2,%3};"
        : "+f"(c[0]), "+f"(c[1]), "+f"(c[2]), "+f"(c[3])
        : "r"(a0), "r"(a1), "r"(a2), "r"(a3), "r"(b0), "r"(b1));
}

// ============================================================================
// tf32 mma.sync GEMM with cp.async 2-stage pipeline.
// C[M,N] = A[M,K] @ B[K,N], fp32 in/out. CTA tile 128x128, BK=32, 256 thr
// (8 warps, warp tile 64x32). M%128==0, N%128==0, K%32==0.
// EPI 0: +bias; EPI 1: elu1; EPI 2: N-split -> C (elu1) / C2 (raw).
// smem: Araw fp32 [128x32] @0 | Braw fp32 [32x128] @16384 |
//       As tf32 [128x36] @32768 | Bs tf32 [32x136] @51200  (68608 B)
// ============================================================================
#define GAP 36
#define GBP 136
#define G_AR 0
#define G_BR 16384
#define G_AS 32768
#define G_BS 51200
#define G_SMEM 68608

template<int EPI>
__device__ __forceinline__ void gemm_issue(uint32_t sb, const float* A,
                                           const float* B, int row0, int col0,
                                           int k0, int N, int K, int tid)
{
    #pragma unroll
    for (int j = 0; j < 4; j++) {
        int idx = tid + 256 * j;
        int r = idx >> 3, c = idx & 7;
        cp16(sb + G_AR + r * 128 + c * 16,
             &A[(size_t)(row0 + r) * K + k0 + c * 4]);
    }
    #pragma unroll
    for (int j = 0; j < 4; j++) {
        int idx = tid + 256 * j;
        int r = idx >> 5, c = idx & 31;
        cp16(sb + G_BR + r * 512 + c * 16,
             &B[(size_t)(k0 + r) * N + col0 + c * 4]);
    }
    CP_COMMIT();
}

template<int EPI>
__global__ __launch_bounds__(256)
void mma_gemm(const float* __restrict__ A, const float* __restrict__ B,
              float* __restrict__ C, float* __restrict__ C2,
              const float* __restrict__ bias, int N, int K)
{
    extern __shared__ char smem[];
    const uint32_t sb = smem_u32(smem);
    float*    Araw = reinterpret_cast<float*>(smem + G_AR);
    float*    Braw = reinterpret_cast<float*>(smem + G_BR);
    uint32_t* As   = reinterpret_cast<uint32_t*>(smem + G_AS);
    uint32_t* Bs   = reinterpret_cast<uint32_t*>(smem + G_BS);

    const int tid  = threadIdx.x;
    const int wid  = tid >> 5;
    const int lane = tid & 31;
    const int wm   = (wid & 1) * 64;
    const int wn   = (wid >> 1) * 32;
    const int row0 = blockIdx.y * 128;
    const int col0 = blockIdx.x * 128;
    const int lr = lane >> 2;
    const int lc = lane & 3;

    float acc[4][4][4];
    #pragma unroll
    for (int i = 0; i < 4; i++)
        #pragma unroll
        for (int j = 0; j < 4; j++)
            #pragma unroll
            for (int r = 0; r < 4; r++) acc[i][j][r] = 0.f;

    gemm_issue<EPI>(sb, A, B, row0, col0, 0, N, K, tid);

    const int ntiles = K / 32;
    for (int kt = 0; kt < ntiles; kt++) {
        CP_WAIT0();
        __syncthreads();

        // convert raw fp32 -> tf32 (rna) into padded compute buffers
        #pragma unroll
        for (int j = 0; j < 4; j++) {
            int idx = tid + 256 * j;
            int r = idx >> 3, c4 = (idx & 7) * 4;
            float4 v = *reinterpret_cast<const float4*>(&Araw[r * 32 + c4]);
            uint4 o;
            o.x = f2tf32(v.x); o.y = f2tf32(v.y);
            o.z = f2tf32(v.z); o.w = f2tf32(v.w);
            *reinterpret_cast<uint4*>(&As[r * GAP + c4]) = o;
        }
        #pragma unroll
        for (int j = 0; j < 4; j++) {
            int idx = tid + 256 * j;
            int r = idx >> 5, c4 = (idx & 31) * 4;
            float4 v = *reinterpret_cast<const float4*>(&Braw[r * 128 + c4]);
            uint4 o;
            o.x = f2tf32(v.x); o.y = f2tf32(v.y);
            o.z = f2tf32(v.z); o.w = f2tf32(v.w);
            *reinterpret_cast<uint4*>(&Bs[r * GBP + c4]) = o;
        }
        __syncthreads();

        if (kt + 1 < ntiles)
            gemm_issue<EPI>(sb, A, B, row0, col0, (kt + 1) * 32, N, K, tid);

        #pragma unroll
        for (int s = 0; s < 4; s++) {
            const int kk = s * 8;
            uint32_t af[4][4];
            #pragma unroll
            for (int mt = 0; mt < 4; mt++) {
                const uint32_t* ap = &As[(wm + mt * 16 + lr) * GAP + kk + lc];
                af[mt][0] = ap[0];
                af[mt][1] = ap[8 * GAP];
                af[mt][2] = ap[4];
                af[mt][3] = ap[8 * GAP + 4];
            }
            uint32_t bf[4][2];
            #pragma unroll
            for (int nt = 0; nt < 4; nt++) {
                const uint32_t* bp = &Bs[(kk + lc) * GBP + wn + nt * 8 + lr];
                bf[nt][0] = bp[0];
                bf[nt][1] = bp[4 * GBP];
            }
            #pragma unroll
            for (int mt = 0; mt < 4; mt++)
                #pragma unroll
                for (int nt = 0; nt < 4; nt++)
                    mma_tf32(acc[mt][nt], af[mt][0], af[mt][1], af[mt][2],
                             af[mt][3], bf[nt][0], bf[nt][1]);
        }
        __syncthreads();
    }

    // ---- epilogue ----
    const int half = N >> 1;
    #pragma unroll
    for (int mt = 0; mt < 4; mt++) {
        #pragma unroll
        for (int nt = 0; nt < 4; nt++) {
            const int col = col0 + wn + nt * 8 + lc * 2;
            #pragma unroll
            for (int hh = 0; hh < 2; hh++) {
                const int row = row0 + wm + mt * 16 + lr + hh * 8;
                float v0 = acc[mt][nt][hh * 2 + 0];
                float v1 = acc[mt][nt][hh * 2 + 1];
                float2 o;
                if (EPI == 0) {
                    o.x = v0 + bias[col]; o.y = v1 + bias[col + 1];
                    *reinterpret_cast<float2*>(&C[(size_t)row * N + col]) = o;
                } else if (EPI == 1) {
                    o.x = elu1(v0); o.y = elu1(v1);
                    *reinterpret_cast<float2*>(&C[(size_t)row * N + col]) = o;
                } else {
                    if (col < half) {
                        o.x = elu1(v0); o.y = elu1(v1);
                        *reinterpret_cast<float2*>(&C[(size_t)row * half + col]) = o;
                    } else {
                        o.x = v0; o.y = v1;
                        *reinterpret_cast<float2*>(&C2[(size_t)row * half + (col - half)]) = o;
                    }
                }
            }
        }
    }
}

// ---------------------------------------------------------------------------
// Zero kv / ksum accumulators
// ---------------------------------------------------------------------------
__global__ void zero_kernel()
{
    int i = blockIdx.x * 256 + threadIdx.x;
    if (i < BATCH*HEADS*DHEAD*DHEAD) g_kv[i] = 0.f;
    if (i < BATCH*HEADS*DHEAD)       g_ksum[i] = 0.f;
}

// ---------------------------------------------------------------------------
// kv[bh][d][m] = sum_n k[b,n,h,d]*v[b,n,h,m];  ksum[bh][d] = sum_n k
// ---------------------------------------------------------------------------
#define CHUNK 512
__global__ __launch_bounds__(256)
void kv_reduce_kernel()
{
    const int bh = blockIdx.x;
    const int b = bh / HEADS, h = bh % HEADS;
    const int n0 = blockIdx.y * CHUNK;
    __shared__ float Ks[32][64];
    __shared__ float Vs[32][64];

    const int tid = threadIdx.x;
    const int m0 = (tid & 15) * 4;
    const int d0 = (tid >> 4) * 4;

    float acc[4][4] = {};
    float sk[4] = {0.f, 0.f, 0.f, 0.f};

    const float* kptr = g_k + ((size_t)b * NSEQ) * INNER + h * DHEAD;
    const float* vptr = g_v + ((size_t)b * NSEQ) * INNER + h * DHEAD;

    for (int nn = n0; nn < n0 + CHUNK; nn += 32) {
        #pragma unroll
        for (int i = tid; i < 32 * 64; i += 256) {
            int r = i >> 6, c = i & 63;
            Ks[r][c] = kptr[(size_t)(nn + r) * INNER + c];
            Vs[r][c] = vptr[(size_t)(nn + r) * INNER + c];
        }
        __syncthreads();
        #pragma unroll
        for (int kk = 0; kk < 32; kk++) {
            float4 k4 = *reinterpret_cast<const float4*>(&Ks[kk][d0]);
            float4 v4 = *reinterpret_cast<const float4*>(&Vs[kk][m0]);
            float ka[4] = {k4.x, k4.y, k4.z, k4.w};
            float va[4] = {v4.x, v4.y, v4.z, v4.w};
            #pragma unroll
            for (int i = 0; i < 4; i++)
                #pragma unroll
                for (int j = 0; j < 4; j++)
                    acc[i][j] += ka[i] * va[j];
            if (m0 == 0) {
                sk[0] += ka[0]; sk[1] += ka[1]; sk[2] += ka[2]; sk[3] += ka[3];
            }
        }
        __syncthreads();
    }

    #pragma unroll
    for (int i = 0; i < 4; i++)
        #pragma unroll
        for (int j = 0; j < 4; j++)
            atomicAdd(&g_kv[((size_t)bh * DHEAD + d0 + i) * DHEAD + m0 + j], acc[i][j]);
    if (m0 == 0) {
        #pragma unroll
        for (int i = 0; i < 4; i++)
            atomicAdd(&g_ksum[bh * DHEAD + d0 + i], sk[i]);
    }
}

// ---------------------------------------------------------------------------
// attn via tf32 mma: attn[n,m] = (q[n,:] @ kv[:,m]) * 1/(q[n,:].ksum + 1e-6)
// Block: one bh, 128 q-rows. A = q (row-major, K=d), B = kv^T ([m][d] col-major).
// 8 warps: warp grid 4(M) x 2(N), warp tile 32x32.
// smem: qs tf32[128x68] @0 | kvs tf32[64x68] @34816 | ks f32[64] @52224 |
//       zr f32[128] @52480   (52992 B)
// ---------------------------------------------------------------------------
#define AQP 68
#define A_QS  0
#define A_KVS 34816
#define A_KS  52224
#define A_ZR  52480
#define A_SMEM 52992

__global__ __launch_bounds__(256)
void attn_mma_kernel()
{
    extern __shared__ char smem[];
    uint32_t* qs  = reinterpret_cast<uint32_t*>(smem + A_QS);
    uint32_t* kvs = reinterpret_cast<uint32_t*>(smem + A_KVS);
    float*    ks  = reinterpret_cast<float*>(smem + A_KS);
    float*    zr  = reinterpret_cast<float*>(smem + A_ZR);

    const int bh = blockIdx.x;
    const int b = bh / HEADS, h = bh % HEADS;
    const int n0 = blockIdx.y * 128;

    const int tid  = threadIdx.x;
    const int wid  = tid >> 5;
    const int lane = tid & 31;
    const int wm   = (wid & 3) * 32;
    const int wn   = (wid >> 2) * 32;
    const int lr = lane >> 2;
    const int lc = lane & 3;

    // load q tile [128 x 64] -> tf32
    const float* qptr = g_q + ((size_t)(b * NSEQ + n0)) * INNER + h * DHEAD;
    #pragma unroll
    for (int j = 0; j < 8; j++) {
        int idx = tid + 256 * j;
        int r = idx >> 4, c4 = (idx & 15) * 4;
        float4 v = *reinterpret_cast<const float4*>(&qptr[(size_t)r * INNER + c4]);
        uint32_t* d = &qs[r * AQP + c4];
        d[0] = f2tf32(v.x); d[1] = f2tf32(v.y);
        d[2] = f2tf32(v.z); d[3] = f2tf32(v.w);
    }
    // load kv [d][m] -> kvs[m][d] (transposed), tf32
    #pragma unroll
    for (int j = 0; j < 4; j++) {
        int idx = tid + 256 * j;
        int d = idx >> 4, m4 = (idx & 15) * 4;
        float4 v = *reinterpret_cast<const float4*>(&g_kv[(size_t)bh * 4096 + d * 64 + m4]);
        kvs[(m4 + 0) * AQP + d] = f2tf32(v.x);
        kvs[(m4 + 1) * AQP + d] = f2tf32(v.y);
        kvs[(m4 + 2) * AQP + d] = f2tf32(v.z);
        kvs[(m4 + 3) * AQP + d] = f2tf32(v.w);
    }
    if (tid < 64) ks[tid] = g_ksum[bh * 64 + tid];
    __syncthreads();

    // z per row
    if (tid < 128) {
        float s = 0.f;
        #pragma unroll
        for (int dd = 0; dd < 64; dd++)
            s += __uint_as_float(qs[tid * AQP + dd]) * ks[dd];
        zr[tid] = 1.f / (s + 1e-6f);
    }
    __syncthreads();

    float acc[2][4][4];
    #pragma unroll
    for (int i = 0; i < 2; i++)
        #pragma unroll
        for (int j = 0; j < 4; j++)
            #pragma unroll
            for (int r = 0; r < 4; r++) acc[i][j][r] = 0.f;

    #pragma unroll
    for (int s = 0; s < 8; s++) {
        const int kk = s * 8;
        uint32_t af[2][4];
        #pragma unroll
        for (int mt = 0; mt < 2; mt++) {
            const uint32_t* ap = &qs[(wm + mt * 16 + lr) * AQP + kk + lc];
            af[mt][0] = ap[0];
            af[mt][1] = ap[8 * AQP];
            af[mt][2] = ap[4];
            af[mt][3] = ap[8 * AQP + 4];
        }
        uint32_t bf[4][2];
        #pragma unroll
        for (int nt = 0; nt < 4; nt++) {
            const uint32_t* bp = &kvs[(wn + nt * 8 + lr) * AQP + kk + lc];
            bf[nt][0] = bp[0];
            bf[nt][1] = bp[4];
        }
        #pragma unroll
        for (int mt = 0; mt < 2; mt++)
            #pragma unroll
            for (int nt = 0; nt < 4; nt++)
                mma_tf32(acc[mt][nt], af[mt][0], af[mt][1], af[mt][2],
                         af[mt][3], bf[nt][0], bf[nt][1]);
    }

    // epilogue: scale by zr[row], store
    #pragma unroll
    for (int mt = 0; mt < 2; mt++) {
        #pragma unroll
        for (int nt = 0; nt < 4; nt++) {
            const int col = wn + nt * 8 + lc * 2;
            #pragma unroll
            for (int hh = 0; hh < 2; hh++) {
                const int row = wm + mt * 16 + lr + hh * 8;
                const float z = zr[row];
                float2 o;
                o.x = acc[mt][nt][hh * 2 + 0] * z;
                o.y = acc[mt][nt][hh * 2 + 1] * z;
                *reinterpret_cast<float2*>(
                    &g_attn[((size_t)(b * NSEQ + n0 + row)) * INNER + h * DHEAD + col]) = o;
            }
        }
    }
}

// ---------------------------------------------------------------------------
extern "C" void kernel_launch(void* const* d_in, const int* in_sizes, int n_in,
                              void* d_out, int out_size)
{
    const float* x_q  = (const float*)d_in[0];
    const float* x_kv = (const float*)d_in[1];
    const float* Wq   = (const float*)d_in[2];
    const float* Wkv  = (const float*)d_in[3];
    const float* Wout = (const float*)d_in[4];
    const float* bout = (const float*)d_in[5];
    float* out = (float*)d_out;

    float *qp, *kp, *vp, *ap;
    cudaGetSymbolAddress((void**)&qp, g_q);
    cudaGetSymbolAddress((void**)&kp, g_k);
    cudaGetSymbolAddress((void**)&vp, g_v);
    cudaGetSymbolAddress((void**)&ap, g_attn);

    cudaFuncSetAttribute(mma_gemm<0>, cudaFuncAttributeMaxDynamicSharedMemorySize, G_SMEM);
    cudaFuncSetAttribute(mma_gemm<1>, cudaFuncAttributeMaxDynamicSharedMemorySize, G_SMEM);
    cudaFuncSetAttribute(mma_gemm<2>, cudaFuncAttributeMaxDynamicSharedMemorySize, G_SMEM);
    cudaFuncSetAttribute(attn_mma_kernel, cudaFuncAttributeMaxDynamicSharedMemorySize, A_SMEM);

    dim3 blk(256);

    // 1) q = elu1(x_q @ Wq)
    mma_gemm<1><<<dim3(INNER/128, ROWS/128), blk, G_SMEM>>>(
        x_q, Wq, qp, nullptr, nullptr, INNER, DIM);

    // 2) kv_proj = x_kv @ Wkv -> k (elu1) / v (raw)
    mma_gemm<2><<<dim3(2*INNER/128, ROWS/128), blk, G_SMEM>>>(
        x_kv, Wkv, kp, vp, nullptr, 2*INNER, DIM);

    // 3) kv = k^T v per (b,h); ksum = sum_n k
    zero_kernel<<<(BATCH*HEADS*DHEAD*DHEAD + 255)/256, blk>>>();
    kv_reduce_kernel<<<dim3(BATCH*HEADS, NSEQ/CHUNK), blk>>>();

    // 4) attn = (q @ kv) * z   (tensor-core)
    attn_mma_kernel<<<dim3(BATCH*HEADS, NSEQ/128), blk, A_SMEM>>>();

    // 5) out = attn @ Wout + bout
    mma_gemm<0><<<dim3(INNER/128, ROWS/128), blk, G_SMEM>>>(
        ap, Wout, out, nullptr, bout, INNER, DIM);
}

// round 5
// speedup vs baseline: 1.7438x; 1.7438x over previous
#include <cuda_runtime.h>
#include <cstdint>

#define BATCH 8
#define NSEQ  4096
#define DIM   384
#define HEADS 6
#define DHEAD 64
#define INNER 384
#define ROWS  (BATCH*NSEQ)   // 32768

// ---- scratch (device globals: no allocation allowed) ----
__device__ float g_q   [ (size_t)ROWS*INNER ];
__device__ float g_k   [ (size_t)ROWS*INNER ];
__device__ float g_v   [ (size_t)ROWS*INNER ];
__device__ float g_attn[ (size_t)ROWS*INNER ];
__device__ float g_kv  [ BATCH*HEADS*DHEAD*DHEAD ];
__device__ float g_ksum[ BATCH*HEADS*DHEAD ];

__device__ __forceinline__ float elu1(float x) {
    return x > 0.f ? x + 1.f : __expf(x);
}

__device__ __forceinline__ uint32_t f2tf32(float x) {
    uint32_t u;
    asm("cvt.rna.tf32.f32 %0, %1;" : "=r"(u) : "f"(x));
    return u;
}

__device__ __forceinline__ void mma_tf32(float c[4], uint32_t a0, uint32_t a1,
                                         uint32_t a2, uint32_t a3,
                                         uint32_t b0, uint32_t b1) {
    asm volatile(
        "mma.sync.aligned.m16n8k8.row.col.f32.tf32.tf32.f32 "
        "{%0,%1,%2,%3}, {%4,%5,%6,%7}, {%8,%9}, {%0,%1,%2,%3};"
        : "+f"(c[0]), "+f"(c[1]), "+f"(c[2]), "+f"(c[3])
        : "r"(a0), "r"(a1), "r"(a2), "r"(a3), "r"(b0), "r"(b1));
}

// ============================================================================
// tf32 mma.sync GEMM (round-3 structure, B-pitch bank fix).
// C[M,N] = A[M,K] @ B[K,N], fp32 in/out. CTA tile 128x128, BK=32, 256 thr
// (8 warps, warp tile 64x32). M%128==0, N%128==0, K%32==0.
// EPI 0: +bias; EPI 1: elu1; EPI 2: N-split -> C (elu1) / C2 (raw).
// ============================================================================
#define APITCH 36    // (4*lr+lc)%32 distinct -> conflict-free A frags
#define BPITCH 136   // (8*lc+lr)%32 distinct -> conflict-free B frags

template<int EPI>
__global__ __launch_bounds__(256)
void mma_gemm(const float* __restrict__ A, const float* __restrict__ B,
              float* __restrict__ C, float* __restrict__ C2,
              const float* __restrict__ bias, int N, int K)
{
    __shared__ uint32_t As[128 * APITCH];   // [m][k], tf32 bits
    __shared__ uint32_t Bs[32  * BPITCH];   // [k][n], tf32 bits

    const int tid  = threadIdx.x;
    const int wid  = tid >> 5;
    const int lane = tid & 31;
    const int wm   = (wid & 1) * 64;
    const int wn   = (wid >> 1) * 32;
    const int row0 = blockIdx.y * 128;
    const int col0 = blockIdx.x * 128;
    const int lr = lane >> 2;
    const int lc = lane & 3;

    float acc[4][4][4];
    #pragma unroll
    for (int i = 0; i < 4; i++)
        #pragma unroll
        for (int j = 0; j < 4; j++)
            #pragma unroll
            for (int r = 0; r < 4; r++) acc[i][j][r] = 0.f;

    for (int k0 = 0; k0 < K; k0 += 32) {
        #pragma unroll
        for (int j = 0; j < 4; j++) {
            int idx = tid + 256 * j;
            int r = idx >> 3, c4 = (idx & 7) * 4;
            float4 v = *reinterpret_cast<const float4*>(
                &A[(size_t)(row0 + r) * K + k0 + c4]);
            uint32_t* dst = &As[r * APITCH + c4];
            dst[0] = f2tf32(v.x); dst[1] = f2tf32(v.y);
            dst[2] = f2tf32(v.z); dst[3] = f2tf32(v.w);
        }
        #pragma unroll
        for (int j = 0; j < 4; j++) {
            int idx = tid + 256 * j;
            int r = idx >> 5, c4 = (idx & 31) * 4;
            float4 v = *reinterpret_cast<const float4*>(
                &B[(size_t)(k0 + r) * N + col0 + c4]);
            uint32_t* dst = &Bs[r * BPITCH + c4];
            dst[0] = f2tf32(v.x); dst[1] = f2tf32(v.y);
            dst[2] = f2tf32(v.z); dst[3] = f2tf32(v.w);
        }
        __syncthreads();

        #pragma unroll
        for (int s = 0; s < 4; s++) {
            const int kk = s * 8;
            uint32_t af[4][4];
            #pragma unroll
            for (int mt = 0; mt < 4; mt++) {
                const uint32_t* ap = &As[(wm + mt * 16 + lr) * APITCH + kk + lc];
                af[mt][0] = ap[0];
                af[mt][1] = ap[8 * APITCH];
                af[mt][2] = ap[4];
                af[mt][3] = ap[8 * APITCH + 4];
            }
            uint32_t bf[4][2];
            #pragma unroll
            for (int nt = 0; nt < 4; nt++) {
                const uint32_t* bp = &Bs[(kk + lc) * BPITCH + wn + nt * 8 + lr];
                bf[nt][0] = bp[0];
                bf[nt][1] = bp[4 * BPITCH];
            }
            #pragma unroll
            for (int mt = 0; mt < 4; mt++)
                #pragma unroll
                for (int nt = 0; nt < 4; nt++)
                    mma_tf32(acc[mt][nt], af[mt][0], af[mt][1], af[mt][2],
                             af[mt][3], bf[nt][0], bf[nt][1]);
        }
        __syncthreads();
    }

    // ---- epilogue ----
    const int half = N >> 1;
    #pragma unroll
    for (int mt = 0; mt < 4; mt++) {
        #pragma unroll
        for (int nt = 0; nt < 4; nt++) {
            const int col = col0 + wn + nt * 8 + lc * 2;
            #pragma unroll
            for (int hh = 0; hh < 2; hh++) {
                const int row = row0 + wm + mt * 16 + lr + hh * 8;
                float v0 = acc[mt][nt][hh * 2 + 0];
                float v1 = acc[mt][nt][hh * 2 + 1];
                float2 o;
                if (EPI == 0) {
                    o.x = v0 + bias[col]; o.y = v1 + bias[col + 1];
                    *reinterpret_cast<float2*>(&C[(size_t)row * N + col]) = o;
                } else if (EPI == 1) {
                    o.x = elu1(v0); o.y = elu1(v1);
                    *reinterpret_cast<float2*>(&C[(size_t)row * N + col]) = o;
                } else {
                    if (col < half) {
                        o.x = elu1(v0); o.y = elu1(v1);
                        *reinterpret_cast<float2*>(&C[(size_t)row * half + col]) = o;
                    } else {
                        o.x = v0; o.y = v1;
                        *reinterpret_cast<float2*>(&C2[(size_t)row * half + (col - half)]) = o;
                    }
                }
            }
        }
    }
}

// ---------------------------------------------------------------------------
// Zero kv / ksum accumulators
// ---------------------------------------------------------------------------
__global__ void zero_kernel()
{
    int i = blockIdx.x * 256 + threadIdx.x;
    if (i < BATCH*HEADS*DHEAD*DHEAD) g_kv[i] = 0.f;
    if (i < BATCH*HEADS*DHEAD)       g_ksum[i] = 0.f;
}

// ---------------------------------------------------------------------------
// kv via tf32 mma:  kv[d][m] = sum_n k[n][d] * v[n][m];  ksum[d] = sum_n k[n][d]
// A = k^T (transposed on smem store, [d][n], pitch 36)
// B = v   (natural [n][m] layout == mma "col" operand, pitch 72: (8lc+lr) banks)
// grid (48 bh, NSEQ/512), 256 thr, 8 warps (2M x 4N), warp tile 32x16.
// Partial results atomically accumulated into g_kv / g_ksum (zeroed first).
// ---------------------------------------------------------------------------
#define KTP 36
#define VSP 72
__global__ __launch_bounds__(256)
void kv_mma_kernel()
{
    __shared__ uint32_t Kt[64 * KTP];   // [d][n] tf32
    __shared__ uint32_t Vs[32 * VSP];   // [n][m] tf32
    __shared__ float red[16][64];

    const int bh = blockIdx.x;
    const int b = bh / HEADS, h = bh % HEADS;
    const int n0 = blockIdx.y * 512;

    const int tid  = threadIdx.x;
    const int wid  = tid >> 5;
    const int lane = tid & 31;
    const int wm   = (wid & 1) * 32;    // d offset
    const int wn   = (wid >> 1) * 16;   // m offset
    const int lr = lane >> 2;
    const int lc = lane & 3;

    const float* kbase = g_k + ((size_t)(b * NSEQ + n0)) * INNER + h * DHEAD;
    const float* vbase = g_v + ((size_t)(b * NSEQ + n0)) * INNER + h * DHEAD;

    float acc[2][2][4];
    #pragma unroll
    for (int i = 0; i < 2; i++)
        #pragma unroll
        for (int j = 0; j < 2; j++)
            #pragma unroll
            for (int r = 0; r < 4; r++) acc[i][j][r] = 0.f;
    float sk[4] = {0.f, 0.f, 0.f, 0.f};

    for (int sub = 0; sub < 16; sub++) {
        const int nn = sub * 32;
        #pragma unroll
        for (int it = 0; it < 2; it++) {
            int idx = tid + it * 256;
            int n = idx >> 4, c4 = (idx & 15) * 4;
            float4 kw = *reinterpret_cast<const float4*>(
                &kbase[(size_t)(nn + n) * INNER + c4]);
            // transposed store: Kt[d][n]
            Kt[(c4 + 0) * KTP + n] = f2tf32(kw.x);
            Kt[(c4 + 1) * KTP + n] = f2tf32(kw.y);
            Kt[(c4 + 2) * KTP + n] = f2tf32(kw.z);
            Kt[(c4 + 3) * KTP + n] = f2tf32(kw.w);
            sk[0] += kw.x; sk[1] += kw.y; sk[2] += kw.z; sk[3] += kw.w;
            float4 vw = *reinterpret_cast<const float4*>(
                &vbase[(size_t)(nn + n) * INNER + c4]);
            uint4 o;
            o.x = f2tf32(vw.x); o.y = f2tf32(vw.y);
            o.z = f2tf32(vw.z); o.w = f2tf32(vw.w);
            *reinterpret_cast<uint4*>(&Vs[n * VSP + c4]) = o;
        }
        __syncthreads();

        #pragma unroll
        for (int s = 0; s < 4; s++) {
            const int kk = s * 8;
            uint32_t af[2][4];
            #pragma unroll
            for (int mt = 0; mt < 2; mt++) {
                const uint32_t* ap = &Kt[(wm + mt * 16 + lr) * KTP + kk + lc];
                af[mt][0] = ap[0];
                af[mt][1] = ap[8 * KTP];
                af[mt][2] = ap[4];
                af[mt][3] = ap[8 * KTP + 4];
            }
            uint32_t bf[2][2];
            #pragma unroll
            for (int nt = 0; nt < 2; nt++) {
                const uint32_t* bp = &Vs[(kk + lc) * VSP + wn + nt * 8 + lr];
                bf[nt][0] = bp[0];
                bf[nt][1] = bp[4 * VSP];
            }
            #pragma unroll
            for (int mt = 0; mt < 2; mt++)
                #pragma unroll
                for (int nt = 0; nt < 2; nt++)
                    mma_tf32(acc[mt][nt], af[mt][0], af[mt][1], af[mt][2],
                             af[mt][3], bf[nt][0], bf[nt][1]);
        }
        __syncthreads();
    }

    // ---- ksum reduction: thread owns d = (tid&15)*4 + j, n-group = tid>>4 ----
    {
        const int c4 = (tid & 15) * 4;
        const int grp = tid >> 4;
        #pragma unroll
        for (int j = 0; j < 4; j++) red[grp][c4 + j] = sk[j];
        __syncthreads();
        if (tid < 64) {
            float s = 0.f;
            #pragma unroll
            for (int r = 0; r < 16; r++) s += red[r][tid];
            atomicAdd(&g_ksum[bh * DHEAD + tid], s);
        }
    }

    // ---- kv accumulation ----
    float* kvp = g_kv + (size_t)bh * DHEAD * DHEAD;
    #pragma unroll
    for (int mt = 0; mt < 2; mt++) {
        #pragma unroll
        for (int nt = 0; nt < 2; nt++) {
            const int col = wn + nt * 8 + lc * 2;
            #pragma unroll
            for (int hh = 0; hh < 2; hh++) {
                const int row = wm + mt * 16 + lr + hh * 8;
                atomicAdd(&kvp[row * DHEAD + col],     acc[mt][nt][hh * 2 + 0]);
                atomicAdd(&kvp[row * DHEAD + col + 1], acc[mt][nt][hh * 2 + 1]);
            }
        }
    }
}

// ---------------------------------------------------------------------------
// attn via tf32 mma: attn[n,m] = (q[n,:] @ kv[:,m]) * 1/(q[n,:].ksum + 1e-6)
// ---------------------------------------------------------------------------
#define AQP 68
#define A_QS  0
#define A_KVS 34816
#define A_KS  52224
#define A_ZR  52480
#define A_SMEM 52992

__global__ __launch_bounds__(256)
void attn_mma_kernel()
{
    extern __shared__ char smem[];
    uint32_t* qs  = reinterpret_cast<uint32_t*>(smem + A_QS);
    uint32_t* kvs = reinterpret_cast<uint32_t*>(smem + A_KVS);
    float*    ks  = reinterpret_cast<float*>(smem + A_KS);
    float*    zr  = reinterpret_cast<float*>(smem + A_ZR);

    const int bh = blockIdx.x;
    const int b = bh / HEADS, h = bh % HEADS;
    const int n0 = blockIdx.y * 128;

    const int tid  = threadIdx.x;
    const int wid  = tid >> 5;
    const int lane = tid & 31;
    const int wm   = (wid & 3) * 32;
    const int wn   = (wid >> 2) * 32;
    const int lr = lane >> 2;
    const int lc = lane & 3;

    const float* qptr = g_q + ((size_t)(b * NSEQ + n0)) * INNER + h * DHEAD;
    #pragma unroll
    for (int j = 0; j < 8; j++) {
        int idx = tid + 256 * j;
        int r = idx >> 4, c4 = (idx & 15) * 4;
        float4 v = *reinterpret_cast<const float4*>(&qptr[(size_t)r * INNER + c4]);
        uint32_t* d = &qs[r * AQP + c4];
        d[0] = f2tf32(v.x); d[1] = f2tf32(v.y);
        d[2] = f2tf32(v.z); d[3] = f2tf32(v.w);
    }
    #pragma unroll
    for (int j = 0; j < 4; j++) {
        int idx = tid + 256 * j;
        int d = idx >> 4, m4 = (idx & 15) * 4;
        float4 v = *reinterpret_cast<const float4*>(&g_kv[(size_t)bh * 4096 + d * 64 + m4]);
        kvs[(m4 + 0) * AQP + d] = f2tf32(v.x);
        kvs[(m4 + 1) * AQP + d] = f2tf32(v.y);
        kvs[(m4 + 2) * AQP + d] = f2tf32(v.z);
        kvs[(m4 + 3) * AQP + d] = f2tf32(v.w);
    }
    if (tid < 64) ks[tid] = g_ksum[bh * 64 + tid];
    __syncthreads();

    if (tid < 128) {
        float s = 0.f;
        #pragma unroll
        for (int dd = 0; dd < 64; dd++)
            s += __uint_as_float(qs[tid * AQP + dd]) * ks[dd];
        zr[tid] = 1.f / (s + 1e-6f);
    }
    __syncthreads();

    float acc[2][4][4];
    #pragma unroll
    for (int i = 0; i < 2; i++)
        #pragma unroll
        for (int j = 0; j < 4; j++)
            #pragma unroll
            for (int r = 0; r < 4; r++) acc[i][j][r] = 0.f;

    #pragma unroll
    for (int s = 0; s < 8; s++) {
        const int kk = s * 8;
        uint32_t af[2][4];
        #pragma unroll
        for (int mt = 0; mt < 2; mt++) {
            const uint32_t* ap = &qs[(wm + mt * 16 + lr) * AQP + kk + lc];
            af[mt][0] = ap[0];
            af[mt][1] = ap[8 * AQP];
            af[mt][2] = ap[4];
            af[mt][3] = ap[8 * AQP + 4];
        }
        uint32_t bf[4][2];
        #pragma unroll
        for (int nt = 0; nt < 4; nt++) {
            const uint32_t* bp = &kvs[(wn + nt * 8 + lr) * AQP + kk + lc];
            bf[nt][0] = bp[0];
            bf[nt][1] = bp[4];
        }
        #pragma unroll
        for (int mt = 0; mt < 2; mt++)
            #pragma unroll
            for (int nt = 0; nt < 4; nt++)
                mma_tf32(acc[mt][nt], af[mt][0], af[mt][1], af[mt][2],
                         af[mt][3], bf[nt][0], bf[nt][1]);
    }

    #pragma unroll
    for (int mt = 0; mt < 2; mt++) {
        #pragma unroll
        for (int nt = 0; nt < 4; nt++) {
            const int col = wn + nt * 8 + lc * 2;
            #pragma unroll
            for (int hh = 0; hh < 2; hh++) {
                const int row = wm + mt * 16 + lr + hh * 8;
                const float z = zr[row];
                float2 o;
                o.x = acc[mt][nt][hh * 2 + 0] * z;
                o.y = acc[mt][nt][hh * 2 + 1] * z;
                *reinterpret_cast<float2*>(
                    &g_attn[((size_t)(b * NSEQ + n0 + row)) * INNER + h * DHEAD + col]) = o;
            }
        }
    }
}

// ---------------------------------------------------------------------------
extern "C" void kernel_launch(void* const* d_in, const int* in_sizes, int n_in,
                              void* d_out, int out_size)
{
    const float* x_q  = (const float*)d_in[0];
    const float* x_kv = (const float*)d_in[1];
    const float* Wq   = (const float*)d_in[2];
    const float* Wkv  = (const float*)d_in[3];
    const float* Wout = (const float*)d_in[4];
    const float* bout = (const float*)d_in[5];
    float* out = (float*)d_out;

    float *qp, *kp, *vp, *ap;
    cudaGetSymbolAddress((void**)&qp, g_q);
    cudaGetSymbolAddress((void**)&kp, g_k);
    cudaGetSymbolAddress((void**)&vp, g_v);
    cudaGetSymbolAddress((void**)&ap, g_attn);

    cudaFuncSetAttribute(attn_mma_kernel, cudaFuncAttributeMaxDynamicSharedMemorySize, A_SMEM);

    dim3 blk(256);

    // 1) q = elu1(x_q @ Wq)
    mma_gemm<1><<<dim3(INNER/128, ROWS/128), blk>>>(
        x_q, Wq, qp, nullptr, nullptr, INNER, DIM);

    // 2) kv_proj = x_kv @ Wkv -> k (elu1) / v (raw)
    mma_gemm<2><<<dim3(2*INNER/128, ROWS/128), blk>>>(
        x_kv, Wkv, kp, vp, nullptr, 2*INNER, DIM);

    // 3) kv = k^T v per (b,h); ksum = sum_n k   (tensor-core + atomics)
    zero_kernel<<<(BATCH*HEADS*DHEAD*DHEAD + 255)/256, blk>>>();
    kv_mma_kernel<<<dim3(BATCH*HEADS, NSEQ/512), blk>>>();

    // 4) attn = (q @ kv) * z   (tensor-core)
    attn_mma_kernel<<<dim3(BATCH*HEADS, NSEQ/128), blk, A_SMEM>>>();

    // 5) out = attn @ Wout + bout
    mma_gemm<0><<<dim3(INNER/128, ROWS/128), blk>>>(
        ap, Wout, out, nullptr, bout, INNER, DIM);
}